// round 11
// baseline (speedup 1.0000x reference)
#include <cuda_runtime.h>
#include <cuda_fp16.h>

// DVGO volume rendering forward pass.
// R11: split-ray — 2 warps per ray (A: samples 0..287, B: 288..557).
//      B scans with local cum, buffers unscaled A/W in 18 regs, rescales by
//      warp A's final transmittance after __syncthreads(). 2-deep eval
//      pipeline per warp (reg-feasible MLP). Zero-padded 162^3 packed grid.

#define NRAYS   8192
#define NSAMP   558
#define HSTART  288     // B-half start (A: 9 chunks of 32)
#define GSZ     160
#define PG      162     // padded grid dim
#define PG2     (PG * PG)
#define PG3     (PG * PG * PG)
#define GSZ3    (GSZ * GSZ * GSZ)

// Packed voxel: .x = density bits, .y = half2(off_r, off_g),
//               .z = half2(off_b, emo_r), .w = half2(emo_g, emo_b)
// Zero-initialized at module load; repack writes only interior [1..160]^3,
// so the one-voxel border stays zero => zero-padding for free.
__device__ uint4 g_pack[PG3];

static __device__ __forceinline__ float sigmoid_fast(float x) {
    return __fdividef(1.0f, 1.0f + __expf(-x));
}

__global__ __launch_bounds__(256)
void repack_kernel(const float* __restrict__ density,
                   const float* __restrict__ off_c,
                   const float* __restrict__ emo_c)
{
    const int v = (blockIdx.x * blockDim.x + threadIdx.x) * 4;
    if (v >= GSZ3) return;

    const float4 d  = __ldg((const float4*)(density + v));
    const float4 o0 = __ldg((const float4*)(off_c + v));
    const float4 o1 = __ldg((const float4*)(off_c + GSZ3 + v));
    const float4 o2 = __ldg((const float4*)(off_c + 2 * GSZ3 + v));
    const float4 e0 = __ldg((const float4*)(emo_c + v));
    const float4 e1 = __ldg((const float4*)(emo_c + GSZ3 + v));
    const float4 e2 = __ldg((const float4*)(emo_c + 2 * GSZ3 + v));

    const float dv[4]  = {d.x,  d.y,  d.z,  d.w};
    const float o0v[4] = {o0.x, o0.y, o0.z, o0.w};
    const float o1v[4] = {o1.x, o1.y, o1.z, o1.w};
    const float o2v[4] = {o2.x, o2.y, o2.z, o2.w};
    const float e0v[4] = {e0.x, e0.y, e0.z, e0.w};
    const float e1v[4] = {e1.x, e1.y, e1.z, e1.w};
    const float e2v[4] = {e2.x, e2.y, e2.z, e2.w};

    const int z0 = v % GSZ;
    const int y  = (v / GSZ) % GSZ;
    const int x  = v / (GSZ * GSZ);
    uint4* dst = &g_pack[(x + 1) * PG2 + (y + 1) * PG + (z0 + 1)];

    #pragma unroll
    for (int j = 0; j < 4; j++) {
        __half2 hA = __halves2half2(__float2half_rn(o0v[j]), __float2half_rn(o1v[j]));
        __half2 hB = __halves2half2(__float2half_rn(o2v[j]), __float2half_rn(e0v[j]));
        __half2 hC = __halves2half2(__float2half_rn(e1v[j]), __float2half_rn(e2v[j]));
        uint4 p;
        p.x = __float_as_uint(dv[j]);
        p.y = *reinterpret_cast<unsigned int*>(&hA);
        p.z = *reinterpret_cast<unsigned int*>(&hB);
        p.w = *reinterpret_cast<unsigned int*>(&hC);
        dst[j] = p;
    }
}

struct RayCtx {
    float ox, oy, oz, dx, dy, dz;
    float tmin, factor, jit;
    bool  ray_mask, on;
};

// Compute alpha + rgb for one sample index s.
static __device__ __forceinline__ void sample_eval(
    const RayCtx& c, int s,
    float& alpha, float& rr, float& gg, float& bb)
{
    const float ACT_SHIFT = -13.815509557964f;   // log(1/(1-1e-6) - 1)

    const float t  = c.tmin + c.factor * ((float)s + c.jit);
    const float px = c.ox + c.dx * t;
    const float py = c.oy + c.dy * t;
    const float pz = c.oz + c.dz * t;

    const bool m = c.ray_mask ||
                   (px < -1.0f) || (px > 1.0f) ||
                   (py < -1.0f) || (py > 1.0f) ||
                   (pz < -1.0f) || (pz > 1.0f);

    const float ix = (px + 1.0f) * 79.5f;
    const float iy = (py + 1.0f) * 79.5f;
    const float iz = (pz + 1.0f) * 79.5f;

    const bool outside = (ix <= -1.0f) || (ix >= 160.0f) ||
                         (iy <= -1.0f) || (iy >= 160.0f) ||
                         (iz <= -1.0f) || (iz >= 160.0f);

    float dens = 0.0f;
    float so0 = 0.f, so1 = 0.f, so2 = 0.f;
    float se0 = 0.f, se1 = 0.f, se2 = 0.f;

    if (!outside) {
        const float flx = floorf(ix), fly = floorf(iy), flz = floorf(iz);
        const float fx = ix - flx, fy = iy - fly, fz = iz - flz;
        // padded-grid base: shift every dim by +1; indices always in-bounds,
        // border voxels are zero -> zero-padding semantics exactly.
        const int base = ((int)flx + 1) * PG2 + ((int)fly + 1) * PG + ((int)flz + 1);

        const float wx0 = 1.0f - fx, wx1 = fx;
        const float wy0 = 1.0f - fy, wy1 = fy;
        const float wz0 = 1.0f - fz, wz1 = fz;

        float w8[8];
        w8[0] = wx0 * wy0 * wz0;
        w8[1] = wx0 * wy0 * wz1;
        w8[2] = wx0 * wy1 * wz0;
        w8[3] = wx0 * wy1 * wz1;
        w8[4] = wx1 * wy0 * wz0;
        w8[5] = wx1 * wy0 * wz1;
        w8[6] = wx1 * wy1 * wz0;
        w8[7] = wx1 * wy1 * wz1;
        const int c8[8] = { base,             base + 1,
                            base + PG,        base + PG + 1,
                            base + PG2,       base + PG2 + 1,
                            base + PG2 + PG,  base + PG2 + PG + 1 };

        #pragma unroll
        for (int k = 0; k < 8; k++) {
            const float w = w8[k];
            const uint4 v = __ldg(&g_pack[c8[k]]);
            dens = fmaf(w, __uint_as_float(v.x), dens);
            const float2 cA = __half22float2(*reinterpret_cast<const __half2*>(&v.y));
            const float2 cB = __half22float2(*reinterpret_cast<const __half2*>(&v.z));
            so0 = fmaf(w, cA.x, so0);
            so1 = fmaf(w, cA.y, so1);
            so2 = fmaf(w, cB.x, so2);
            if (c.on) {
                const float2 cC = __half22float2(*reinterpret_cast<const __half2*>(&v.w));
                se0 = fmaf(w, cB.y, se0);
                se1 = fmaf(w, cC.x, se1);
                se2 = fmaf(w, cC.y, se2);
            }
        }
    }

    alpha = 0.0f;
    if (!m) {
        const float x  = dens + ACT_SHIFT;
        const float sp = (x > 0.0f) ? (x + log1pf(expf(-x))) : log1pf(expf(x));
        const float tt = sp * 0.5f;   // always tiny (< ~1e-6) here
        // Correctly-rounded exp(-tt) near 1:  e = fl(1 + (-tt + tt^2/2)).
        // The single rounding in (1.0f + u) matches the reference's
        // fp32 `1 - exp(...)` quantization; alpha = 1 - e is exact.
        const float u = fmaf(0.5f * tt, tt, -tt);
        alpha = 1.0f - (1.0f + u);
    }

    rr = sigmoid_fast(so0);
    gg = sigmoid_fast(so1);
    bb = sigmoid_fast(so2);
    if (c.on) {
        rr += sigmoid_fast(se0);
        gg += sigmoid_fast(se1);
        bb += sigmoid_fast(se2);
    }
}

__global__ __launch_bounds__(128)
void dvgo_kernel(const float* __restrict__ rays_o,
                 const float* __restrict__ rays_d,
                 const float* __restrict__ jitter,
                 const int*   __restrict__ em_modes,
                 float* __restrict__ out)
{
    __shared__ __align__(16) float rgbbuf[4][96];
    __shared__ float s_cumA[2];
    __shared__ float s_m[2][3];

    const int lane = threadIdx.x & 31;
    const int wl   = threadIdx.x >> 5;     // warp in block, 0..3
    const int ri   = wl >> 1;              // ray in block, 0..1
    const int half = wl & 1;               // 0 = front half, 1 = back half
    const int r    = blockIdx.x * 2 + ri;

    // Output segment pointers (tuple flattened in order)
    float* __restrict__ A   = out + (size_t)r * (NSAMP + 1);
    float* __restrict__ W   = out + (size_t)NRAYS * (NSAMP + 1) + (size_t)r * NSAMP;
    float* __restrict__ L   = out + (size_t)NRAYS * (2 * NSAMP + 1);
    float* __restrict__ RGB = L + NRAYS + (size_t)r * NSAMP * 3;
    float* __restrict__ M   = L + NRAYS + (size_t)NRAYS * NSAMP * 3;

    RayCtx c;
    c.ox = rays_o[3 * r + 0]; c.oy = rays_o[3 * r + 1]; c.oz = rays_o[3 * r + 2];
    c.dx = rays_d[3 * r + 0]; c.dy = rays_d[3 * r + 1]; c.dz = rays_d[3 * r + 2];
    c.jit = jitter[r];
    c.on  = (em_modes[r] == 1);   // warp-uniform

    // --- AABB intersection (match reference exactly) ---
    const float vx = (c.dx == 0.0f) ? 1e-6f : c.dx;
    const float vy = (c.dy == 0.0f) ? 1e-6f : c.dy;
    const float vz = (c.dz == 0.0f) ? 1e-6f : c.dz;
    const float rax = (1.0f - c.ox) / vx, rbx = (-1.0f - c.ox) / vx;
    const float ray_ = (1.0f - c.oy) / vy, rby = (-1.0f - c.oy) / vy;
    const float raz = (1.0f - c.oz) / vz, rbz = (-1.0f - c.oz) / vz;
    float tmin = fmaxf(fmaxf(fminf(rax, rbx), fminf(ray_, rby)), fminf(raz, rbz));
    float tmax = fminf(fminf(fmaxf(rax, rbx), fmaxf(ray_, rby)), fmaxf(raz, rbz));
    tmin = fminf(fmaxf(tmin, 0.05f), 6.0f);
    tmax = fminf(fmaxf(tmax, 0.05f), 6.0f);
    c.ray_mask = (tmax <= tmin);
    c.tmin = tmin;

    const float dnorm = sqrtf(c.dx * c.dx + c.dy * c.dy + c.dz * c.dz);
    c.factor = 0.00625f / dnorm;  // STEPSIZE * VOXEL_SIZE / |d|

    float cum = 1.0f;               // transmittance over THIS half (local)
    float accr = 0.f, accg = 0.f, accb = 0.f;

    // stage one full chunk of rgb in smem, write coalesced float2 stcs
    auto rgb_store = [&](int s0, float rr, float gg, float bb) {
        rgbbuf[wl][lane * 3 + 0] = rr;
        rgbbuf[wl][lane * 3 + 1] = gg;
        rgbbuf[wl][lane * 3 + 2] = bb;
        __syncwarp();
        float2* dst = (float2*)(RGB + (size_t)s0 * 3);
        const float2* src = (const float2*)rgbbuf[wl];
        __stcs(dst + lane, src[lane]);
        if (lane < 16) __stcs(dst + 32 + lane, src[32 + lane]);
        __syncwarp();
    };

    // warp scan of p; returns incl/excl, updates cum
    auto scan = [&](float alpha, float& incl, float& excl) {
        const float p = fmaxf(1.0f - alpha, 1e-10f);
        incl = p;
        #pragma unroll
        for (int d = 1; d < 32; d <<= 1) {
            const float v = __shfl_up_sync(0xFFFFFFFFu, incl, d);
            if (lane >= d) incl *= v;
        }
        excl = __shfl_up_sync(0xFFFFFFFFu, incl, 1);
        if (lane == 0) excl = 1.0f;
    };

    float aL[9], wL[9];   // B-half buffers (unscaled per-lane A/W values)

    if (half == 0) {
        // ---- front half: samples 0..287, 9 chunks, direct stores ----
        if (lane == 0) A[0] = 1.0f;

        auto chunkA = [&](int s0, float alpha, float rr, float gg, float bb) {
            float incl, excl;
            scan(alpha, incl, excl);
            const float w = alpha * cum * excl;
            __stcs(&A[1 + s0 + lane], cum * incl);
            __stcs(&W[s0 + lane], w);
            accr += w * rr; accg += w * gg; accb += w * bb;
            rgb_store(s0, rr, gg, bb);
            cum *= __shfl_sync(0xFFFFFFFFu, incl, 31);
        };

        #pragma unroll 1
        for (int s0 = 0; s0 < 256; s0 += 64) {
            float aA, rA, gA, bA, aB, rB, gB, bB;
            sample_eval(c, s0 + lane,      aA, rA, gA, bA);
            sample_eval(c, s0 + 32 + lane, aB, rB, gB, bB);
            chunkA(s0,      aA, rA, gA, bA);
            chunkA(s0 + 32, aB, rB, gB, bB);
        }
        {
            float a, rr, gg, bb;
            sample_eval(c, 256 + lane, a, rr, gg, bb);
            chunkA(256, a, rr, gg, bb);
        }

        // publish final transmittance + marched partial
        #pragma unroll
        for (int d = 16; d > 0; d >>= 1) {
            accr += __shfl_xor_sync(0xFFFFFFFFu, accr, d);
            accg += __shfl_xor_sync(0xFFFFFFFFu, accg, d);
            accb += __shfl_xor_sync(0xFFFFFFFFu, accb, d);
        }
        if (lane == 0) {
            s_cumA[ri] = cum;
            s_m[ri][0] = accr; s_m[ri][1] = accg; s_m[ri][2] = accb;
        }
    } else {
        // ---- back half: samples 288..557, local cum, buffered A/W ----
        #pragma unroll
        for (int q = 0; q < 4; q++) {
            const int s0 = HSTART + q * 64;
            float aA, rA, gA, bA, aB, rB, gB, bB;
            sample_eval(c, s0 + lane,      aA, rA, gA, bA);
            sample_eval(c, s0 + 32 + lane, aB, rB, gB, bB);
            {
                float incl, excl;
                scan(aA, incl, excl);
                aL[2 * q] = cum * incl;
                const float w = aA * cum * excl;
                wL[2 * q] = w;
                accr += w * rA; accg += w * gA; accb += w * bA;
                rgb_store(s0, rA, gA, bA);
                cum *= __shfl_sync(0xFFFFFFFFu, incl, 31);
            }
            {
                float incl, excl;
                scan(aB, incl, excl);
                aL[2 * q + 1] = cum * incl;
                const float w = aB * cum * excl;
                wL[2 * q + 1] = w;
                accr += w * rB; accg += w * gB; accb += w * bB;
                rgb_store(s0 + 32, rB, gB, bB);
                cum *= __shfl_sync(0xFFFFFFFFu, incl, 31);
            }
        }
        // tail: samples 544..557 (14 lanes)
        {
            const int  s      = 544 + lane;
            const bool active = (s < NSAMP);
            float alpha = 0.f, rr = 0.f, gg = 0.f, bb = 0.f;
            if (active) sample_eval(c, s, alpha, rr, gg, bb);

            float incl, excl;
            scan(active ? alpha : 0.0f, incl, excl);
            aL[8] = cum * incl;
            const float w = alpha * cum * excl;
            wL[8] = w;
            if (active) {
                const size_t ro = (size_t)s * 3;
                __stcs(&RGB[ro + 0], rr);
                __stcs(&RGB[ro + 1], gg);
                __stcs(&RGB[ro + 2], bb);
                accr += w * rr; accg += w * gg; accb += w * bb;
            }
            cum *= __shfl_sync(0xFFFFFFFFu, incl, 31);
        }
    }

    __syncthreads();

    if (half == 1) {
        // rescale buffered values by front half's transmittance and store
        const float cA = s_cumA[ri];
        #pragma unroll
        for (int k = 0; k < 8; k++) {
            __stcs(&A[1 + HSTART + k * 32 + lane], cA * aL[k]);
            __stcs(&W[HSTART + k * 32 + lane], cA * wL[k]);
        }
        if (544 + lane < NSAMP) {
            __stcs(&A[1 + 544 + lane], cA * aL[8]);
            __stcs(&W[544 + lane], cA * wL[8]);
        }

        #pragma unroll
        for (int d = 16; d > 0; d >>= 1) {
            accr += __shfl_xor_sync(0xFFFFFFFFu, accr, d);
            accg += __shfl_xor_sync(0xFFFFFFFFu, accg, d);
            accb += __shfl_xor_sync(0xFFFFFFFFu, accb, d);
        }
        if (lane == 0) {
            L[r] = cA * cum;
            M[3 * r + 0] = s_m[ri][0] + cA * accr;
            M[3 * r + 1] = s_m[ri][1] + cA * accg;
            M[3 * r + 2] = s_m[ri][2] + cA * accb;
        }
    }
}

extern "C" void kernel_launch(void* const* d_in, const int* in_sizes, int n_in,
                              void* d_out, int out_size)
{
    const float* rays_o   = (const float*)d_in[0];
    const float* rays_d   = (const float*)d_in[1];
    const float* jitter   = (const float*)d_in[2];
    const int*   em_modes = (const int*)  d_in[3];
    const float* density  = (const float*)d_in[4];
    const float* off_c    = (const float*)d_in[5];
    const float* emo_c    = (const float*)d_in[6];
    float* out = (float*)d_out;

    repack_kernel<<<GSZ3 / 4 / 256, 256>>>(density, off_c, emo_c);
    // 8192 rays, TWO warps each (front/back half), 2 rays per 128-thr block
    dvgo_kernel<<<NRAYS / 2, 128>>>(rays_o, rays_d, jitter, em_modes, out);
}

// round 12
// speedup vs baseline: 1.2349x; 1.2349x over previous
#include <cuda_runtime.h>
#include <cuda_fp16.h>

// DVGO volume rendering forward pass.
// R12: R9 structure (one warp/ray, 2-deep eval pipeline, zero-padded 162^3
//      packed grid) with 64-thread blocks for finer scheduling granularity.

#define NRAYS   8192
#define NSAMP   558
#define NPAIR   512     // 8 pairs of 32-sample chunks
#define NFULL   544     // 17 * 32
#define GSZ     160
#define PG      162     // padded grid dim
#define PG2     (PG * PG)
#define PG3     (PG * PG * PG)
#define GSZ3    (GSZ * GSZ * GSZ)

// Packed voxel: .x = density bits, .y = half2(off_r, off_g),
//               .z = half2(off_b, emo_r), .w = half2(emo_g, emo_b)
// Zero-initialized at module load; repack writes only interior [1..160]^3,
// so the one-voxel border stays zero => zero-padding for free.
__device__ uint4 g_pack[PG3];

static __device__ __forceinline__ float sigmoid_fast(float x) {
    return __fdividef(1.0f, 1.0f + __expf(-x));
}

__global__ __launch_bounds__(256)
void repack_kernel(const float* __restrict__ density,
                   const float* __restrict__ off_c,
                   const float* __restrict__ emo_c)
{
    const int v = (blockIdx.x * blockDim.x + threadIdx.x) * 4;
    if (v >= GSZ3) return;

    const float4 d  = __ldg((const float4*)(density + v));
    const float4 o0 = __ldg((const float4*)(off_c + v));
    const float4 o1 = __ldg((const float4*)(off_c + GSZ3 + v));
    const float4 o2 = __ldg((const float4*)(off_c + 2 * GSZ3 + v));
    const float4 e0 = __ldg((const float4*)(emo_c + v));
    const float4 e1 = __ldg((const float4*)(emo_c + GSZ3 + v));
    const float4 e2 = __ldg((const float4*)(emo_c + 2 * GSZ3 + v));

    const float dv[4]  = {d.x,  d.y,  d.z,  d.w};
    const float o0v[4] = {o0.x, o0.y, o0.z, o0.w};
    const float o1v[4] = {o1.x, o1.y, o1.z, o1.w};
    const float o2v[4] = {o2.x, o2.y, o2.z, o2.w};
    const float e0v[4] = {e0.x, e0.y, e0.z, e0.w};
    const float e1v[4] = {e1.x, e1.y, e1.z, e1.w};
    const float e2v[4] = {e2.x, e2.y, e2.z, e2.w};

    const int z0 = v % GSZ;
    const int y  = (v / GSZ) % GSZ;
    const int x  = v / (GSZ * GSZ);
    uint4* dst = &g_pack[(x + 1) * PG2 + (y + 1) * PG + (z0 + 1)];

    #pragma unroll
    for (int j = 0; j < 4; j++) {
        __half2 hA = __halves2half2(__float2half_rn(o0v[j]), __float2half_rn(o1v[j]));
        __half2 hB = __halves2half2(__float2half_rn(o2v[j]), __float2half_rn(e0v[j]));
        __half2 hC = __halves2half2(__float2half_rn(e1v[j]), __float2half_rn(e2v[j]));
        uint4 p;
        p.x = __float_as_uint(dv[j]);
        p.y = *reinterpret_cast<unsigned int*>(&hA);
        p.z = *reinterpret_cast<unsigned int*>(&hB);
        p.w = *reinterpret_cast<unsigned int*>(&hC);
        dst[j] = p;
    }
}

struct RayCtx {
    float ox, oy, oz, dx, dy, dz;
    float tmin, factor, jit;
    bool  ray_mask, on;
};

// Compute alpha + rgb for one sample index s.
static __device__ __forceinline__ void sample_eval(
    const RayCtx& c, int s,
    float& alpha, float& rr, float& gg, float& bb)
{
    const float ACT_SHIFT = -13.815509557964f;   // log(1/(1-1e-6) - 1)

    const float t  = c.tmin + c.factor * ((float)s + c.jit);
    const float px = c.ox + c.dx * t;
    const float py = c.oy + c.dy * t;
    const float pz = c.oz + c.dz * t;

    const bool m = c.ray_mask ||
                   (px < -1.0f) || (px > 1.0f) ||
                   (py < -1.0f) || (py > 1.0f) ||
                   (pz < -1.0f) || (pz > 1.0f);

    const float ix = (px + 1.0f) * 79.5f;
    const float iy = (py + 1.0f) * 79.5f;
    const float iz = (pz + 1.0f) * 79.5f;

    const bool outside = (ix <= -1.0f) || (ix >= 160.0f) ||
                         (iy <= -1.0f) || (iy >= 160.0f) ||
                         (iz <= -1.0f) || (iz >= 160.0f);

    float dens = 0.0f;
    float so0 = 0.f, so1 = 0.f, so2 = 0.f;
    float se0 = 0.f, se1 = 0.f, se2 = 0.f;

    if (!outside) {
        const float flx = floorf(ix), fly = floorf(iy), flz = floorf(iz);
        const float fx = ix - flx, fy = iy - fly, fz = iz - flz;
        // padded-grid base: shift every dim by +1; indices always in-bounds,
        // border voxels are zero -> zero-padding semantics exactly.
        const int base = ((int)flx + 1) * PG2 + ((int)fly + 1) * PG + ((int)flz + 1);

        const float wx0 = 1.0f - fx, wx1 = fx;
        const float wy0 = 1.0f - fy, wy1 = fy;
        const float wz0 = 1.0f - fz, wz1 = fz;

        float w8[8];
        w8[0] = wx0 * wy0 * wz0;
        w8[1] = wx0 * wy0 * wz1;
        w8[2] = wx0 * wy1 * wz0;
        w8[3] = wx0 * wy1 * wz1;
        w8[4] = wx1 * wy0 * wz0;
        w8[5] = wx1 * wy0 * wz1;
        w8[6] = wx1 * wy1 * wz0;
        w8[7] = wx1 * wy1 * wz1;
        const int c8[8] = { base,             base + 1,
                            base + PG,        base + PG + 1,
                            base + PG2,       base + PG2 + 1,
                            base + PG2 + PG,  base + PG2 + PG + 1 };

        #pragma unroll
        for (int k = 0; k < 8; k++) {
            const float w = w8[k];
            const uint4 v = __ldg(&g_pack[c8[k]]);
            dens = fmaf(w, __uint_as_float(v.x), dens);
            const float2 cA = __half22float2(*reinterpret_cast<const __half2*>(&v.y));
            const float2 cB = __half22float2(*reinterpret_cast<const __half2*>(&v.z));
            so0 = fmaf(w, cA.x, so0);
            so1 = fmaf(w, cA.y, so1);
            so2 = fmaf(w, cB.x, so2);
            if (c.on) {
                const float2 cC = __half22float2(*reinterpret_cast<const __half2*>(&v.w));
                se0 = fmaf(w, cB.y, se0);
                se1 = fmaf(w, cC.x, se1);
                se2 = fmaf(w, cC.y, se2);
            }
        }
    }

    alpha = 0.0f;
    if (!m) {
        const float x  = dens + ACT_SHIFT;
        const float sp = (x > 0.0f) ? (x + log1pf(expf(-x))) : log1pf(expf(x));
        const float tt = sp * 0.5f;   // always tiny (< ~1e-6) here
        // Correctly-rounded exp(-tt) near 1:  e = fl(1 + (-tt + tt^2/2)).
        // The single rounding in (1.0f + u) matches the reference's
        // fp32 `1 - exp(...)` quantization; alpha = 1 - e is exact.
        const float u = fmaf(0.5f * tt, tt, -tt);
        alpha = 1.0f - (1.0f + u);
    }

    rr = sigmoid_fast(so0);
    gg = sigmoid_fast(so1);
    bb = sigmoid_fast(so2);
    if (c.on) {
        rr += sigmoid_fast(se0);
        gg += sigmoid_fast(se1);
        bb += sigmoid_fast(se2);
    }
}

__global__ __launch_bounds__(64)
void dvgo_kernel(const float* __restrict__ rays_o,
                 const float* __restrict__ rays_d,
                 const float* __restrict__ jitter,
                 const int*   __restrict__ em_modes,
                 float* __restrict__ out)
{
    __shared__ __align__(16) float rgbbuf[2][96];

    const int warp = (blockIdx.x * blockDim.x + threadIdx.x) >> 5;
    const int lane = threadIdx.x & 31;
    const int wl   = threadIdx.x >> 5;
    if (warp >= NRAYS) return;
    const int r = warp;

    // Output segment pointers (tuple flattened in order)
    float* __restrict__ A   = out + (size_t)r * (NSAMP + 1);
    float* __restrict__ W   = out + (size_t)NRAYS * (NSAMP + 1) + (size_t)r * NSAMP;
    float* __restrict__ L   = out + (size_t)NRAYS * (2 * NSAMP + 1);
    float* __restrict__ RGB = L + NRAYS + (size_t)r * NSAMP * 3;
    float* __restrict__ M   = L + NRAYS + (size_t)NRAYS * NSAMP * 3;

    RayCtx c;
    c.ox = rays_o[3 * r + 0]; c.oy = rays_o[3 * r + 1]; c.oz = rays_o[3 * r + 2];
    c.dx = rays_d[3 * r + 0]; c.dy = rays_d[3 * r + 1]; c.dz = rays_d[3 * r + 2];
    c.jit = jitter[r];
    c.on  = (em_modes[r] == 1);   // warp-uniform

    // --- AABB intersection (match reference exactly) ---
    const float vx = (c.dx == 0.0f) ? 1e-6f : c.dx;
    const float vy = (c.dy == 0.0f) ? 1e-6f : c.dy;
    const float vz = (c.dz == 0.0f) ? 1e-6f : c.dz;
    const float rax = (1.0f - c.ox) / vx, rbx = (-1.0f - c.ox) / vx;
    const float ray_ = (1.0f - c.oy) / vy, rby = (-1.0f - c.oy) / vy;
    const float raz = (1.0f - c.oz) / vz, rbz = (-1.0f - c.oz) / vz;
    float tmin = fmaxf(fmaxf(fminf(rax, rbx), fminf(ray_, rby)), fminf(raz, rbz));
    float tmax = fminf(fminf(fmaxf(rax, rbx), fmaxf(ray_, rby)), fmaxf(raz, rbz));
    tmin = fminf(fmaxf(tmin, 0.05f), 6.0f);
    tmax = fminf(fmaxf(tmax, 0.05f), 6.0f);
    c.ray_mask = (tmax <= tmin);
    c.tmin = tmin;

    const float dnorm = sqrtf(c.dx * c.dx + c.dy * c.dy + c.dz * c.dz);
    c.factor = 0.00625f / dnorm;  // STEPSIZE * VOXEL_SIZE / |d|

    if (lane == 0) A[0] = 1.0f;

    float cum = 1.0f;               // running transmittance (uniform across warp)
    float accr = 0.f, accg = 0.f, accb = 0.f;

    // scan + all outputs for one full 32-sample chunk starting at s0
    auto scan_out = [&](int s0, float alpha, float rr, float gg, float bb) {
        const float p = fmaxf(1.0f - alpha, 1e-10f);
        float incl = p;
        #pragma unroll
        for (int d = 1; d < 32; d <<= 1) {
            const float v = __shfl_up_sync(0xFFFFFFFFu, incl, d);
            if (lane >= d) incl *= v;
        }
        float excl = __shfl_up_sync(0xFFFFFFFFu, incl, 1);
        if (lane == 0) excl = 1.0f;

        const float w = alpha * cum * excl;
        __stcs(&A[1 + s0 + lane], cum * incl);
        __stcs(&W[s0 + lane], w);
        accr += w * rr;
        accg += w * gg;
        accb += w * bb;

        rgbbuf[wl][lane * 3 + 0] = rr;
        rgbbuf[wl][lane * 3 + 1] = gg;
        rgbbuf[wl][lane * 3 + 2] = bb;
        __syncwarp();
        float2* dst = (float2*)(RGB + (size_t)s0 * 3);
        const float2* src = (const float2*)rgbbuf[wl];
        __stcs(dst + lane, src[lane]);
        if (lane < 16) __stcs(dst + 32 + lane, src[32 + lane]);
        __syncwarp();

        cum *= __shfl_sync(0xFFFFFFFFu, incl, 31);
    };

    // 8 pairs of chunks: both evals issued before either scan (gather MLP x2)
    for (int s0 = 0; s0 < NPAIR; s0 += 64) {
        float aA, rA, gA, bA, aB, rB, gB, bB;
        sample_eval(c, s0 + lane,      aA, rA, gA, bA);
        sample_eval(c, s0 + 32 + lane, aB, rB, gB, bB);
        scan_out(s0,      aA, rA, gA, bA);
        scan_out(s0 + 32, aB, rB, gB, bB);
    }

    // chunk 17 (samples 512..543)
    {
        float a, rr, gg, bb;
        sample_eval(c, NPAIR + lane, a, rr, gg, bb);
        scan_out(NPAIR, a, rr, gg, bb);
    }

    // ---- tail: samples 544..557 (14 lanes active) ----
    {
        const int  s      = NFULL + lane;
        const bool active = (s < NSAMP);

        float alpha = 0.f, rr = 0.f, gg = 0.f, bb = 0.f;
        if (active) sample_eval(c, s, alpha, rr, gg, bb);

        const float p = active ? fmaxf(1.0f - alpha, 1e-10f) : 1.0f;
        float incl = p;
        #pragma unroll
        for (int d = 1; d < 32; d <<= 1) {
            const float v = __shfl_up_sync(0xFFFFFFFFu, incl, d);
            if (lane >= d) incl *= v;
        }
        float excl = __shfl_up_sync(0xFFFFFFFFu, incl, 1);
        if (lane == 0) excl = 1.0f;

        if (active) {
            const float w = alpha * cum * excl;
            __stcs(&A[1 + s], cum * incl);
            __stcs(&W[s], w);
            const size_t ro = (size_t)s * 3;
            __stcs(&RGB[ro + 0], rr);
            __stcs(&RGB[ro + 1], gg);
            __stcs(&RGB[ro + 2], bb);
            accr += w * rr;
            accg += w * gg;
            accb += w * bb;
        }
        cum *= __shfl_sync(0xFFFFFFFFu, incl, 31);
    }

    // reduce rgb_marched across lanes
    #pragma unroll
    for (int d = 16; d > 0; d >>= 1) {
        accr += __shfl_xor_sync(0xFFFFFFFFu, accr, d);
        accg += __shfl_xor_sync(0xFFFFFFFFu, accg, d);
        accb += __shfl_xor_sync(0xFFFFFFFFu, accb, d);
    }
    if (lane == 0) {
        L[r] = cum;
        M[3 * r + 0] = accr;
        M[3 * r + 1] = accg;
        M[3 * r + 2] = accb;
    }
}

extern "C" void kernel_launch(void* const* d_in, const int* in_sizes, int n_in,
                              void* d_out, int out_size)
{
    const float* rays_o   = (const float*)d_in[0];
    const float* rays_d   = (const float*)d_in[1];
    const float* jitter   = (const float*)d_in[2];
    const int*   em_modes = (const int*)  d_in[3];
    const float* density  = (const float*)d_in[4];
    const float* off_c    = (const float*)d_in[5];
    const float* emo_c    = (const float*)d_in[6];
    float* out = (float*)d_out;

    repack_kernel<<<GSZ3 / 4 / 256, 256>>>(density, off_c, emo_c);
    // 8192 rays, one warp each, 2 warps per block -> 4096 blocks
    dvgo_kernel<<<NRAYS / 2, 64>>>(rays_o, rays_d, jitter, em_modes, out);
}